// round 14
// baseline (speedup 1.0000x reference)
#include <cuda_runtime.h>
#include <math.h>

#define B_    8
#define S_    4096
#define H_    512
#define NBLK  128
#define NSLOT (S_ + 1)

#define OUT_HID  ((size_t)B_ * S_ * H_)        // 16,777,216
#define OUT_CELL (OUT_HID + 2 * B_ * H_)       // +8192

// ---------------- device-global scratch (allocation-free) ----------------
__device__ __align__(16) float d_proj[(size_t)32768 * 960];   // relu(world@Wp^T + bp)
__device__ __align__(16) float d_g0in[(size_t)32768 * 2048];  // input-side layer0 gates
__device__ __align__(16) float d_embg[32 * 2048];             // emb@Wih0_act^T + bih0 + bhh0
__device__ __align__(16) float d_h0buf[2][B_][H_];
__device__ __align__(16) float d_h1buf[2][B_][H_];
__device__ __align__(16) int   d_aidx32[B_ * S_];
__device__ unsigned d_barcnt;
__device__ unsigned d_bargen;

// ---------------- packed f32x2 helpers ----------------
__device__ __forceinline__ unsigned long long fma2(unsigned long long a,
                                                   unsigned long long b,
                                                   unsigned long long c) {
    unsigned long long d;
    asm("fma.rn.f32x2 %0, %1, %2, %3;" : "=l"(d) : "l"(a), "l"(b), "l"(c));
    return d;
}
__device__ __forceinline__ unsigned long long pack2(float x, float y) {
    unsigned long long d;
    asm("mov.b64 %0, {%1, %2};" : "=l"(d) : "f"(x), "f"(y));
    return d;
}
__device__ __forceinline__ float2 unpack2(unsigned long long v) {
    float2 r;
    asm("mov.b64 {%0, %1}, %2;" : "=f"(r.x), "=f"(r.y) : "l"(v));
    return r;
}
__device__ __forceinline__ float fsig(float x) { return 1.0f / (1.0f + __expf(-x)); }
__device__ __forceinline__ float ftanh(float x) { return 2.0f * fsig(2.0f * x) - 1.0f; }

// ============================================================
// reset: zero h buffers + barrier state (runs every replay)
// ============================================================
__global__ void reset_kernel() {
    int i = blockIdx.x * blockDim.x + threadIdx.x;
    if (i == 0) { d_barcnt = 0; d_bargen = 0; }
    if (i < 2 * B_ * H_) {
        ((float*)d_h0buf)[i] = 0.0f;
        ((float*)d_h1buf)[i] = 0.0f;
    }
}

// ============================================================
// idx: 4-way dtype detection (int64 / float32 / float64 / int32)
// + masked conversion to int32. For each candidate encoding we
// test "every element is integral and in [0,32)". The encodings
// are mutually exclusive on non-degenerate data:
//   - ints read as floats -> denormals (floor != value)
//   - floats read as ints -> huge magnitudes
//   - f32 pairs read as f64 (and vice versa) -> non-integral/huge
// Indices are masked &31 so gathers can never go OOB.
// ============================================================
__global__ void idx_kernel(const void* __restrict__ raw) {
    __shared__ int ok64, okf32, okf64;
    if (threadIdx.x == 0) { ok64 = 1; okf32 = 1; okf64 = 1; }
    __syncthreads();
    const long long* p64 = (const long long*)raw;
    const int*       p32 = (const int*)raw;
    // 8-byte interpretations: exactly 128 KB read (valid for int32/f32 too)
    for (int k = threadIdx.x; k < B_ * S_ / 2; k += blockDim.x) {
        long long v = p64[k];
        if (v < 0 || v >= 32) ok64 = 0;
        double d = __longlong_as_double(v);
        if (!(d >= 0.0 && d < 32.0 && d == floor(d))) okf64 = 0;
    }
    // 4-byte interpretation as float32
    for (int k = threadIdx.x; k < B_ * S_; k += blockDim.x) {
        float f = __int_as_float(p32[k]);
        if (!(f >= 0.0f && f < 32.0f && f == floorf(f))) okf32 = 0;
    }
    __syncthreads();
    if (ok64) {
        for (int k = threadIdx.x; k < B_ * S_; k += blockDim.x)
            d_aidx32[k] = ((int)p64[k]) & 31;
    } else if (okf32) {
        for (int k = threadIdx.x; k < B_ * S_; k += blockDim.x)
            d_aidx32[k] = ((int)__int_as_float(p32[k])) & 31;
    } else if (okf64) {
        for (int k = threadIdx.x; k < B_ * S_ / 2; k += blockDim.x) {
            // one f64 per logical element
        }
        for (int k = threadIdx.x; k < B_ * S_; k += blockDim.x)
            d_aidx32[k] = ((int)__longlong_as_double(p64[k])) & 31;
    } else {  // int32
        for (int k = threadIdx.x; k < B_ * S_; k += blockDim.x)
            d_aidx32[k] = p32[k] & 31;
    }
}

// ============================================================
// embg[a][n] = sum_j emb[a][j] * Wih0[n][960+j] + bih0[n] + bhh0[n]
// ============================================================
__global__ void embg_kernel(const float* __restrict__ emb, const float* __restrict__ Wih0,
                            const float* __restrict__ bih0, const float* __restrict__ bhh0) {
    int n = blockIdx.x * blockDim.x + threadIdx.x;   // 0..2047
    int a = blockIdx.y;                              // 0..31
    float s = bih0[n] + bhh0[n];
    const float* w = Wih0 + (size_t)n * 1024 + 960;
    const float* e = emb + a * 64;
#pragma unroll 16
    for (int j = 0; j < 64; j++) s += e[j] * w[j];
    d_embg[a * 2048 + n] = s;
}

// ============================================================
// NT GEMM: C[m][n] = dot(A[m, 0:K], W[n, 0:K])  (+epilogue)
// mode 0: C = relu(acc + bias[n]),          C ld = N
// mode 1: C = acc + embg[d_aidx32[m]][n],   C ld = 2048
// BM=BN=128, BK=16, 256 threads, 8x8 micro-tile, f32x2 FFMA
// ============================================================
__global__ __launch_bounds__(256, 2)
void gemm_nt(const float* __restrict__ A, const float* __restrict__ W,
             const float* __restrict__ bias,
             float* __restrict__ C, int N, int K, int ldw, int mode) {
    __shared__ __align__(16) float As[16][132];
    __shared__ __align__(16) float Ws[16][132];
    int tid = threadIdx.x;
    int m0 = blockIdx.x * 128, n0 = blockIdx.y * 128;
    int tx = tid & 15, ty = tid >> 4;

    unsigned long long acc[8][4];
#pragma unroll
    for (int i = 0; i < 8; i++)
#pragma unroll
        for (int j = 0; j < 4; j++) acc[i][j] = 0ULL;

    for (int k0 = 0; k0 < K; k0 += 16) {
#pragma unroll
        for (int j = 0; j < 2; j++) {
            int id = tid + 256 * j;               // 0..511
            int row = id >> 2, c4 = (id & 3) * 4;
            float4 v = *(const float4*)&A[(size_t)(m0 + row) * K + k0 + c4];
            As[c4 + 0][row] = v.x; As[c4 + 1][row] = v.y;
            As[c4 + 2][row] = v.z; As[c4 + 3][row] = v.w;
        }
#pragma unroll
        for (int j = 0; j < 2; j++) {
            int id = tid + 256 * j;
            int row = id >> 2, c4 = (id & 3) * 4;
            float4 v = make_float4(0.f, 0.f, 0.f, 0.f);
            if (n0 + row < N)
                v = *(const float4*)&W[(size_t)(n0 + row) * ldw + k0 + c4];
            Ws[c4 + 0][row] = v.x; Ws[c4 + 1][row] = v.y;
            Ws[c4 + 2][row] = v.z; Ws[c4 + 3][row] = v.w;
        }
        __syncthreads();
#pragma unroll
        for (int k = 0; k < 16; k++) {
            float __align__(16) a[8];
            *(float4*)&a[0] = *(const float4*)&As[k][ty * 8];
            *(float4*)&a[4] = *(const float4*)&As[k][ty * 8 + 4];
            ulonglong2 w01 = *(const ulonglong2*)&Ws[k][tx * 8];
            ulonglong2 w23 = *(const ulonglong2*)&Ws[k][tx * 8 + 4];
#pragma unroll
            for (int i = 0; i < 8; i++) {
                unsigned long long a2 = pack2(a[i], a[i]);
                acc[i][0] = fma2(a2, w01.x, acc[i][0]);
                acc[i][1] = fma2(a2, w01.y, acc[i][1]);
                acc[i][2] = fma2(a2, w23.x, acc[i][2]);
                acc[i][3] = fma2(a2, w23.y, acc[i][3]);
            }
        }
        __syncthreads();
    }

#pragma unroll
    for (int i = 0; i < 8; i++) {
        int m = m0 + ty * 8 + i;
        float __align__(16) c[8];
#pragma unroll
        for (int j = 0; j < 4; j++) {
            float2 p = unpack2(acc[i][j]);
            c[2 * j] = p.x; c[2 * j + 1] = p.y;
        }
        if (mode == 0) {
#pragma unroll
            for (int j = 0; j < 8; j++) {
                int n = n0 + tx * 8 + j;
                if (n < N) {
                    float v = c[j] + __ldg(&bias[n]);
                    C[(size_t)m * N + n] = fmaxf(v, 0.0f);
                }
            }
        } else {
            int a = d_aidx32[m];                       // pre-masked to [0,31]
            const float* eg = d_embg + (size_t)a * 2048 + n0 + tx * 8;
#pragma unroll
            for (int j = 0; j < 8; j++) c[j] += __ldg(&eg[j]);
            *(float4*)&C[(size_t)m * 2048 + n0 + tx * 8] = *(float4*)&c[0];
            *(float4*)&C[(size_t)m * 2048 + n0 + tx * 8 + 4] = *(float4*)&c[4];
        }
    }
}

// ============================================================
// Grid barrier with proper acquire/release semantics.
// __syncthreads makes all block writes visible to thread 0;
// atom.release publishes them chip-wide; pollers use ld.acquire.
// The barcnt reset is sequenced before the bargen release-store,
// so no next-generation arrival can race the reset.
// ============================================================
__device__ __forceinline__ void gridbar(unsigned gen) {
    __syncthreads();
    if (threadIdx.x == 0) {
        unsigned a;
        asm volatile("atom.release.gpu.global.add.u32 %0, [%1], %2;"
                     : "=r"(a) : "l"(&d_barcnt), "r"(1u) : "memory");
        if (a == NBLK - 1) {
            asm volatile("st.relaxed.gpu.global.u32 [%0], %1;"
                         :: "l"(&d_barcnt), "r"(0u) : "memory");
            asm volatile("st.release.gpu.global.u32 [%0], %1;"
                         :: "l"(&d_bargen), "r"(gen) : "memory");
        } else {
            unsigned g;
            do {
                asm volatile("ld.acquire.gpu.global.u32 %0, [%1];"
                             : "=r"(g) : "l"(&d_bargen) : "memory");
            } while (g < gen);
        }
    }
    __syncthreads();
}

#define WS0 516
#define WS1 1044
#define HS  1044

__global__ __launch_bounds__(256, 1)
void lstm_persistent(const float* __restrict__ Whh0, const float* __restrict__ Wih1,
                     const float* __restrict__ Whh1, const float* __restrict__ bih1,
                     const float* __restrict__ bhh1, float* __restrict__ out) {
    extern __shared__ float sm[];
    float* sW0  = sm;                   // 16 * 516  = 8256
    float* sW1  = sW0 + 16 * WS0;       // 16 * 1044 = 16704
    float* sHc  = sW1 + 16 * WS1;       // 8 * 1044  = 8352 ([0:512)=h0prev, [512:1024)=h1(t-2))
    float* sRed = sHc + 8 * HS;         // 2*16*8*33 = 8448
    float* sGat = sRed + 8448;          // 2*4*4*8   = 256
    float* sC   = sGat + 256;           // 64
    float* sB1  = sC + 64;              // 16

    const int tid = threadIdx.x, bk = blockIdx.x;
    const int ubase = bk * 4;

    // ---- load this block's recurrent weights into SMEM ----
    for (int idx = tid; idx < 2048; idx += 256) {       // Whh0: 16 rows x 512
        int rr = idx >> 7, c4 = (idx & 127) * 4;
        int grow = ((rr >> 2) << 9) + ubase + (rr & 3);
        *(float4*)&sW0[rr * WS0 + c4] = *(const float4*)&Whh0[(size_t)grow * 512 + c4];
    }
    for (int idx = tid; idx < 4096; idx += 256) {       // [Wih1|Whh1]: 16 rows x 1024
        int rr = idx >> 8, k = (idx & 255) * 4;
        int grow = ((rr >> 2) << 9) + ubase + (rr & 3);
        float4 v = (k < 512) ? *(const float4*)&Wih1[(size_t)grow * 512 + k]
                             : *(const float4*)&Whh1[(size_t)grow * 512 + k - 512];
        *(float4*)&sW1[rr * WS1 + k] = v;
    }
    if (tid < 16) {
        int grow = ((tid >> 2) << 9) + ubase + (tid & 3);
        sB1[tid] = bih1[grow] + bhh1[grow];
    }
    if (tid < 64) sC[tid] = 0.0f;
    __syncthreads();

    // dot-phase thread roles (warps 0-3: layer0, warps 4-7: layer1)
    const int L = tid >> 7;
    const int t2 = tid & 127;
    const int rg = t2 >> 5, seg = t2 & 31;
    const float* wbase = (L == 0) ? (sW0 + rg * 4 * WS0) : (sW1 + rg * 4 * WS1);
    const int wstr = (L == 0) ? WS0 : WS1;
    const int niter = (L == 0) ? 4 : 8;

    for (int t = 0; t < NSLOT; t++) {
        // ---- stage h0(t-1), h1(t-2) from L2 (bypass stale L1) ----
        const int p0 = (t + 1) & 1, p1 = t & 1;
        for (int idx = tid; idx < 2048; idx += 256) {
            int b = (idx >> 7) & 7, c4 = (idx & 127) * 4;
            if (idx < 1024)
                *(float4*)&sHc[b * HS + c4] = __ldcg((const float4*)&d_h0buf[p0][b][c4]);
            else
                *(float4*)&sHc[b * HS + 512 + c4] = __ldcg((const float4*)&d_h1buf[p1][b][c4]);
        }
        __syncthreads();

        // ---- dot products: 4 rows x 8 batches per thread ----
        bool act = (L == 0) ? (t < S_) : (t > 0);
        if (act) {
            unsigned long long acc[4][8];
#pragma unroll
            for (int r = 0; r < 4; r++)
#pragma unroll
                for (int b = 0; b < 8; b++) acc[r][b] = 0ULL;

            for (int i = 0; i < niter; i++) {
                int k = (seg << 2) + (i << 7);
                ulonglong2 w0v = *(const ulonglong2*)(wbase + k);
                ulonglong2 w1v = *(const ulonglong2*)(wbase + wstr + k);
                ulonglong2 w2v = *(const ulonglong2*)(wbase + 2 * wstr + k);
                ulonglong2 w3v = *(const ulonglong2*)(wbase + 3 * wstr + k);
#pragma unroll
                for (int b = 0; b < 8; b++) {
                    ulonglong2 h = *(const ulonglong2*)(sHc + b * HS + k);
                    acc[0][b] = fma2(w0v.x, h.x, acc[0][b]);
                    acc[0][b] = fma2(w0v.y, h.y, acc[0][b]);
                    acc[1][b] = fma2(w1v.x, h.x, acc[1][b]);
                    acc[1][b] = fma2(w1v.y, h.y, acc[1][b]);
                    acc[2][b] = fma2(w2v.x, h.x, acc[2][b]);
                    acc[2][b] = fma2(w2v.y, h.y, acc[2][b]);
                    acc[3][b] = fma2(w3v.x, h.x, acc[3][b]);
                    acc[3][b] = fma2(w3v.y, h.y, acc[3][b]);
                }
            }
#pragma unroll
            for (int r = 0; r < 4; r++)
#pragma unroll
                for (int b = 0; b < 8; b++) {
                    float2 p = unpack2(acc[r][b]);
                    sRed[((L * 16 + rg * 4 + r) * 8 + b) * 33 + seg] = p.x + p.y;
                }
        }
        __syncthreads();

        // ---- combine partials -> gate values ----
        {
            int Lc = tid >> 7, rm = (tid >> 3) & 15, b = tid & 7;
            bool actc = (Lc == 0) ? (t < S_) : (t > 0);
            if (actc) {
                const float* rp = sRed + ((Lc * 16 + rm) * 8 + b) * 33;
                float v = 0.0f;
#pragma unroll
                for (int s3 = 0; s3 < 32; s3++) v += rp[s3];
                int g = rm >> 2, j = rm & 3;
                if (Lc == 0)
                    v += __ldg(&d_g0in[((size_t)b * S_ + t) * 2048 + (g << 9) + ubase + j]);
                else
                    v += sB1[rm];
                sGat[Lc * 128 + g * 32 + j * 8 + b] = v;
            }
        }
        __syncthreads();

        // ---- LSTM cell update + h/out writes ----
        if (tid < 64) {
            int Lc = tid >> 5, j = (tid >> 3) & 3, b = tid & 7;
            bool actc = (Lc == 0) ? (t < S_) : (t > 0);
            if (actc) {
                int base = Lc * 128 + j * 8 + b;
                float gi = sGat[base], gf = sGat[base + 32];
                float gg = sGat[base + 64], go = sGat[base + 96];
                float c = fsig(gf) * sC[Lc * 32 + j * 8 + b] + fsig(gi) * ftanh(gg);
                float h = fsig(go) * ftanh(c);
                sC[Lc * 32 + j * 8 + b] = c;
                int u = ubase + j;
                if (Lc == 0) {
                    d_h0buf[t & 1][b][u] = h;
                    if (t == S_ - 1) out[OUT_HID + (size_t)b * H_ + u] = h;
                } else {
                    int tau = t - 1;
                    d_h1buf[tau & 1][b][u] = h;
                    out[((size_t)b * S_ + tau) * H_ + u] = h;
                    if (tau == S_ - 1) out[OUT_HID + (size_t)B_ * H_ + (size_t)b * H_ + u] = h;
                }
            }
        }
        gridbar((unsigned)(t + 1));
    }

    // ---- final cell states ----
    if (tid < 64) {
        int Lc = tid >> 5, j = (tid >> 3) & 3, b = tid & 7;
        out[OUT_CELL + (size_t)Lc * B_ * H_ + (size_t)b * H_ + ubase + j] = sC[Lc * 32 + j * 8 + b];
    }
}

// ============================================================
extern "C" void kernel_launch(void* const* d_in, const int* in_sizes, int n_in,
                              void* d_out, int out_size) {
    const float* world = (const float*)d_in[0];
    const void*  aidx  = (const void*)d_in[1];
    const float* emb   = (const float*)d_in[2];
    const float* Wp    = (const float*)d_in[3];
    const float* bp    = (const float*)d_in[4];
    const float* Wih0  = (const float*)d_in[5];
    const float* Whh0  = (const float*)d_in[6];
    const float* bih0  = (const float*)d_in[7];
    const float* bhh0  = (const float*)d_in[8];
    const float* Wih1  = (const float*)d_in[9];
    const float* Whh1  = (const float*)d_in[10];
    const float* bih1  = (const float*)d_in[11];
    const float* bhh1  = (const float*)d_in[12];
    float* out = (float*)d_out;

    float *proj_p = nullptr, *g0in_p = nullptr;
    cudaGetSymbolAddress((void**)&proj_p, d_proj);
    cudaGetSymbolAddress((void**)&g0in_p, d_g0in);

    const int smem_bytes = (16 * WS0 + 16 * WS1 + 8 * HS + 8448 + 256 + 64 + 16) * 4;
    cudaFuncSetAttribute(lstm_persistent, cudaFuncAttributeMaxDynamicSharedMemorySize, smem_bytes);

    reset_kernel<<<32, 256>>>();
    idx_kernel<<<1, 256>>>(aidx);
    embg_kernel<<<dim3(8, 32), 256>>>(emb, Wih0, bih0, bhh0);
    // proj[32768,960] = relu(world[32768,512] @ Wp[960,512]^T + bp)
    gemm_nt<<<dim3(256, 8), 256>>>(world, Wp, bp, proj_p, 960, 512, 512, 0);
    // g0in[32768,2048] = proj @ Wih0[:, :960]^T + embg[aidx]
    gemm_nt<<<dim3(256, 16), 256>>>(proj_p, Wih0, nullptr, g0in_p, 2048, 960, 1024, 1);
    lstm_persistent<<<NBLK, 256, smem_bytes>>>(Whh0, Wih1, Whh1, bih1, bhh1, out);
}

// round 15
// speedup vs baseline: 1.0002x; 1.0002x over previous
#include <cuda_runtime.h>
#include <math.h>

#define B_    8
#define S_    4096
#define H_    512
#define NBLK  128
#define NSLOT (S_ + 1)

#define OUT_HID  ((size_t)B_ * S_ * H_)        // 16,777,216
#define OUT_CELL (OUT_HID + 2 * B_ * H_)       // +8192

// ---------------- device-global scratch (allocation-free) ----------------
__device__ __align__(16) float d_proj[(size_t)32768 * 960];   // relu(world@Wp^T + bp)
__device__ __align__(16) float d_g0in[(size_t)32768 * 2048];  // input-side layer0 gates
__device__ __align__(16) float d_embg[32 * 2048];             // emb@Wih0_act^T + bih0 + bhh0
__device__ __align__(16) float d_h0buf[2][B_][H_];
__device__ __align__(16) float d_h1buf[2][B_][H_];
__device__ __align__(16) int   d_aidx32[B_ * S_];
__device__ unsigned d_barcnt;
__device__ unsigned d_bargen;

// ---------------- packed f32x2 helpers ----------------
__device__ __forceinline__ unsigned long long fma2(unsigned long long a,
                                                   unsigned long long b,
                                                   unsigned long long c) {
    unsigned long long d;
    asm("fma.rn.f32x2 %0, %1, %2, %3;" : "=l"(d) : "l"(a), "l"(b), "l"(c));
    return d;
}
__device__ __forceinline__ unsigned long long pack2(float x, float y) {
    unsigned long long d;
    asm("mov.b64 %0, {%1, %2};" : "=l"(d) : "f"(x), "f"(y));
    return d;
}
__device__ __forceinline__ float2 unpack2(unsigned long long v) {
    float2 r;
    asm("mov.b64 {%0, %1}, %2;" : "=f"(r.x), "=f"(r.y) : "l"(v));
    return r;
}
__device__ __forceinline__ float fsig(float x) { return 1.0f / (1.0f + __expf(-x)); }
__device__ __forceinline__ float ftanh(float x) { return 2.0f * fsig(2.0f * x) - 1.0f; }

// ============================================================
// reset: zero h buffers + barrier state (runs every replay)
// ============================================================
__global__ void reset_kernel() {
    int i = blockIdx.x * blockDim.x + threadIdx.x;
    if (i == 0) { d_barcnt = 0; d_bargen = 0; }
    if (i < 2 * B_ * H_) {
        ((float*)d_h0buf)[i] = 0.0f;
        ((float*)d_h1buf)[i] = 0.0f;
    }
}

// ============================================================
// idx: 4-way dtype detection (int64 / float32 / float64 / int32)
// + masked conversion to int32. For each candidate encoding we
// test "every element is integral and in [0,32)". The encodings
// are mutually exclusive on non-degenerate data:
//   - ints read as floats -> denormals (floor != value)
//   - floats read as ints -> huge magnitudes
//   - f32 pairs read as f64 (and vice versa) -> non-integral/huge
// Indices are masked &31 so gathers can never go OOB.
// ============================================================
__global__ void idx_kernel(const void* __restrict__ raw) {
    __shared__ int ok64, okf32, okf64;
    if (threadIdx.x == 0) { ok64 = 1; okf32 = 1; okf64 = 1; }
    __syncthreads();
    const long long* p64 = (const long long*)raw;
    const int*       p32 = (const int*)raw;
    // 8-byte interpretations: exactly 128 KB read (valid for int32/f32 too)
    for (int k = threadIdx.x; k < B_ * S_ / 2; k += blockDim.x) {
        long long v = p64[k];
        if (v < 0 || v >= 32) ok64 = 0;
        double d = __longlong_as_double(v);
        if (!(d >= 0.0 && d < 32.0 && d == floor(d))) okf64 = 0;
    }
    // 4-byte interpretation as float32
    for (int k = threadIdx.x; k < B_ * S_; k += blockDim.x) {
        float f = __int_as_float(p32[k]);
        if (!(f >= 0.0f && f < 32.0f && f == floorf(f))) okf32 = 0;
    }
    __syncthreads();
    if (ok64) {
        for (int k = threadIdx.x; k < B_ * S_; k += blockDim.x)
            d_aidx32[k] = ((int)p64[k]) & 31;
    } else if (okf32) {
        for (int k = threadIdx.x; k < B_ * S_; k += blockDim.x)
            d_aidx32[k] = ((int)__int_as_float(p32[k])) & 31;
    } else if (okf64) {
        for (int k = threadIdx.x; k < B_ * S_ / 2; k += blockDim.x) {
            // one f64 per logical element
        }
        for (int k = threadIdx.x; k < B_ * S_; k += blockDim.x)
            d_aidx32[k] = ((int)__longlong_as_double(p64[k])) & 31;
    } else {  // int32
        for (int k = threadIdx.x; k < B_ * S_; k += blockDim.x)
            d_aidx32[k] = p32[k] & 31;
    }
}

// ============================================================
// embg[a][n] = sum_j emb[a][j] * Wih0[n][960+j] + bih0[n] + bhh0[n]
// ============================================================
__global__ void embg_kernel(const float* __restrict__ emb, const float* __restrict__ Wih0,
                            const float* __restrict__ bih0, const float* __restrict__ bhh0) {
    int n = blockIdx.x * blockDim.x + threadIdx.x;   // 0..2047
    int a = blockIdx.y;                              // 0..31
    float s = bih0[n] + bhh0[n];
    const float* w = Wih0 + (size_t)n * 1024 + 960;
    const float* e = emb + a * 64;
#pragma unroll 16
    for (int j = 0; j < 64; j++) s += e[j] * w[j];
    d_embg[a * 2048 + n] = s;
}

// ============================================================
// NT GEMM: C[m][n] = dot(A[m, 0:K], W[n, 0:K])  (+epilogue)
// mode 0: C = relu(acc + bias[n]),          C ld = N
// mode 1: C = acc + embg[d_aidx32[m]][n],   C ld = 2048
// BM=BN=128, BK=16, 256 threads, 8x8 micro-tile, f32x2 FFMA
// ============================================================
__global__ __launch_bounds__(256, 2)
void gemm_nt(const float* __restrict__ A, const float* __restrict__ W,
             const float* __restrict__ bias,
             float* __restrict__ C, int N, int K, int ldw, int mode) {
    __shared__ __align__(16) float As[16][132];
    __shared__ __align__(16) float Ws[16][132];
    int tid = threadIdx.x;
    int m0 = blockIdx.x * 128, n0 = blockIdx.y * 128;
    int tx = tid & 15, ty = tid >> 4;

    unsigned long long acc[8][4];
#pragma unroll
    for (int i = 0; i < 8; i++)
#pragma unroll
        for (int j = 0; j < 4; j++) acc[i][j] = 0ULL;

    for (int k0 = 0; k0 < K; k0 += 16) {
#pragma unroll
        for (int j = 0; j < 2; j++) {
            int id = tid + 256 * j;               // 0..511
            int row = id >> 2, c4 = (id & 3) * 4;
            float4 v = *(const float4*)&A[(size_t)(m0 + row) * K + k0 + c4];
            As[c4 + 0][row] = v.x; As[c4 + 1][row] = v.y;
            As[c4 + 2][row] = v.z; As[c4 + 3][row] = v.w;
        }
#pragma unroll
        for (int j = 0; j < 2; j++) {
            int id = tid + 256 * j;
            int row = id >> 2, c4 = (id & 3) * 4;
            float4 v = make_float4(0.f, 0.f, 0.f, 0.f);
            if (n0 + row < N)
                v = *(const float4*)&W[(size_t)(n0 + row) * ldw + k0 + c4];
            Ws[c4 + 0][row] = v.x; Ws[c4 + 1][row] = v.y;
            Ws[c4 + 2][row] = v.z; Ws[c4 + 3][row] = v.w;
        }
        __syncthreads();
#pragma unroll
        for (int k = 0; k < 16; k++) {
            float __align__(16) a[8];
            *(float4*)&a[0] = *(const float4*)&As[k][ty * 8];
            *(float4*)&a[4] = *(const float4*)&As[k][ty * 8 + 4];
            ulonglong2 w01 = *(const ulonglong2*)&Ws[k][tx * 8];
            ulonglong2 w23 = *(const ulonglong2*)&Ws[k][tx * 8 + 4];
#pragma unroll
            for (int i = 0; i < 8; i++) {
                unsigned long long a2 = pack2(a[i], a[i]);
                acc[i][0] = fma2(a2, w01.x, acc[i][0]);
                acc[i][1] = fma2(a2, w01.y, acc[i][1]);
                acc[i][2] = fma2(a2, w23.x, acc[i][2]);
                acc[i][3] = fma2(a2, w23.y, acc[i][3]);
            }
        }
        __syncthreads();
    }

#pragma unroll
    for (int i = 0; i < 8; i++) {
        int m = m0 + ty * 8 + i;
        float __align__(16) c[8];
#pragma unroll
        for (int j = 0; j < 4; j++) {
            float2 p = unpack2(acc[i][j]);
            c[2 * j] = p.x; c[2 * j + 1] = p.y;
        }
        if (mode == 0) {
#pragma unroll
            for (int j = 0; j < 8; j++) {
                int n = n0 + tx * 8 + j;
                if (n < N) {
                    float v = c[j] + __ldg(&bias[n]);
                    C[(size_t)m * N + n] = fmaxf(v, 0.0f);
                }
            }
        } else {
            int a = d_aidx32[m];                       // pre-masked to [0,31]
            const float* eg = d_embg + (size_t)a * 2048 + n0 + tx * 8;
#pragma unroll
            for (int j = 0; j < 8; j++) c[j] += __ldg(&eg[j]);
            *(float4*)&C[(size_t)m * 2048 + n0 + tx * 8] = *(float4*)&c[0];
            *(float4*)&C[(size_t)m * 2048 + n0 + tx * 8 + 4] = *(float4*)&c[4];
        }
    }
}

// ============================================================
// Grid barrier with proper acquire/release semantics.
// __syncthreads makes all block writes visible to thread 0;
// atom.release publishes them chip-wide; pollers use ld.acquire.
// The barcnt reset is sequenced before the bargen release-store,
// so no next-generation arrival can race the reset.
// ============================================================
__device__ __forceinline__ void gridbar(unsigned gen) {
    __syncthreads();
    if (threadIdx.x == 0) {
        unsigned a;
        asm volatile("atom.release.gpu.global.add.u32 %0, [%1], %2;"
                     : "=r"(a) : "l"(&d_barcnt), "r"(1u) : "memory");
        if (a == NBLK - 1) {
            asm volatile("st.relaxed.gpu.global.u32 [%0], %1;"
                         :: "l"(&d_barcnt), "r"(0u) : "memory");
            asm volatile("st.release.gpu.global.u32 [%0], %1;"
                         :: "l"(&d_bargen), "r"(gen) : "memory");
        } else {
            unsigned g;
            do {
                asm volatile("ld.acquire.gpu.global.u32 %0, [%1];"
                             : "=r"(g) : "l"(&d_bargen) : "memory");
            } while (g < gen);
        }
    }
    __syncthreads();
}

#define WS0 516
#define WS1 1044
#define HS  1044

__global__ __launch_bounds__(256, 1)
void lstm_persistent(const float* __restrict__ Whh0, const float* __restrict__ Wih1,
                     const float* __restrict__ Whh1, const float* __restrict__ bih1,
                     const float* __restrict__ bhh1, float* __restrict__ out) {
    extern __shared__ float sm[];
    float* sW0  = sm;                   // 16 * 516  = 8256
    float* sW1  = sW0 + 16 * WS0;       // 16 * 1044 = 16704
    float* sHc  = sW1 + 16 * WS1;       // 8 * 1044  = 8352 ([0:512)=h0prev, [512:1024)=h1(t-2))
    float* sRed = sHc + 8 * HS;         // 2*16*8*33 = 8448
    float* sGat = sRed + 8448;          // 2*4*4*8   = 256
    float* sC   = sGat + 256;           // 64
    float* sB1  = sC + 64;              // 16

    const int tid = threadIdx.x, bk = blockIdx.x;
    const int ubase = bk * 4;

    // ---- load this block's recurrent weights into SMEM ----
    for (int idx = tid; idx < 2048; idx += 256) {       // Whh0: 16 rows x 512
        int rr = idx >> 7, c4 = (idx & 127) * 4;
        int grow = ((rr >> 2) << 9) + ubase + (rr & 3);
        *(float4*)&sW0[rr * WS0 + c4] = *(const float4*)&Whh0[(size_t)grow * 512 + c4];
    }
    for (int idx = tid; idx < 4096; idx += 256) {       // [Wih1|Whh1]: 16 rows x 1024
        int rr = idx >> 8, k = (idx & 255) * 4;
        int grow = ((rr >> 2) << 9) + ubase + (rr & 3);
        float4 v = (k < 512) ? *(const float4*)&Wih1[(size_t)grow * 512 + k]
                             : *(const float4*)&Whh1[(size_t)grow * 512 + k - 512];
        *(float4*)&sW1[rr * WS1 + k] = v;
    }
    if (tid < 16) {
        int grow = ((tid >> 2) << 9) + ubase + (tid & 3);
        sB1[tid] = bih1[grow] + bhh1[grow];
    }
    if (tid < 64) sC[tid] = 0.0f;
    __syncthreads();

    // dot-phase thread roles (warps 0-3: layer0, warps 4-7: layer1)
    const int L = tid >> 7;
    const int t2 = tid & 127;
    const int rg = t2 >> 5, seg = t2 & 31;
    const float* wbase = (L == 0) ? (sW0 + rg * 4 * WS0) : (sW1 + rg * 4 * WS1);
    const int wstr = (L == 0) ? WS0 : WS1;
    const int niter = (L == 0) ? 4 : 8;

    for (int t = 0; t < NSLOT; t++) {
        // ---- stage h0(t-1), h1(t-2) from L2 (bypass stale L1) ----
        const int p0 = (t + 1) & 1, p1 = t & 1;
        for (int idx = tid; idx < 2048; idx += 256) {
            int b = (idx >> 7) & 7, c4 = (idx & 127) * 4;
            if (idx < 1024)
                *(float4*)&sHc[b * HS + c4] = __ldcg((const float4*)&d_h0buf[p0][b][c4]);
            else
                *(float4*)&sHc[b * HS + 512 + c4] = __ldcg((const float4*)&d_h1buf[p1][b][c4]);
        }
        __syncthreads();

        // ---- dot products: 4 rows x 8 batches per thread ----
        bool act = (L == 0) ? (t < S_) : (t > 0);
        if (act) {
            unsigned long long acc[4][8];
#pragma unroll
            for (int r = 0; r < 4; r++)
#pragma unroll
                for (int b = 0; b < 8; b++) acc[r][b] = 0ULL;

            for (int i = 0; i < niter; i++) {
                int k = (seg << 2) + (i << 7);
                ulonglong2 w0v = *(const ulonglong2*)(wbase + k);
                ulonglong2 w1v = *(const ulonglong2*)(wbase + wstr + k);
                ulonglong2 w2v = *(const ulonglong2*)(wbase + 2 * wstr + k);
                ulonglong2 w3v = *(const ulonglong2*)(wbase + 3 * wstr + k);
#pragma unroll
                for (int b = 0; b < 8; b++) {
                    ulonglong2 h = *(const ulonglong2*)(sHc + b * HS + k);
                    acc[0][b] = fma2(w0v.x, h.x, acc[0][b]);
                    acc[0][b] = fma2(w0v.y, h.y, acc[0][b]);
                    acc[1][b] = fma2(w1v.x, h.x, acc[1][b]);
                    acc[1][b] = fma2(w1v.y, h.y, acc[1][b]);
                    acc[2][b] = fma2(w2v.x, h.x, acc[2][b]);
                    acc[2][b] = fma2(w2v.y, h.y, acc[2][b]);
                    acc[3][b] = fma2(w3v.x, h.x, acc[3][b]);
                    acc[3][b] = fma2(w3v.y, h.y, acc[3][b]);
                }
            }
#pragma unroll
            for (int r = 0; r < 4; r++)
#pragma unroll
                for (int b = 0; b < 8; b++) {
                    float2 p = unpack2(acc[r][b]);
                    sRed[((L * 16 + rg * 4 + r) * 8 + b) * 33 + seg] = p.x + p.y;
                }
        }
        __syncthreads();

        // ---- combine partials -> gate values ----
        {
            int Lc = tid >> 7, rm = (tid >> 3) & 15, b = tid & 7;
            bool actc = (Lc == 0) ? (t < S_) : (t > 0);
            if (actc) {
                const float* rp = sRed + ((Lc * 16 + rm) * 8 + b) * 33;
                float v = 0.0f;
#pragma unroll
                for (int s3 = 0; s3 < 32; s3++) v += rp[s3];
                int g = rm >> 2, j = rm & 3;
                if (Lc == 0)
                    v += __ldg(&d_g0in[((size_t)b * S_ + t) * 2048 + (g << 9) + ubase + j]);
                else
                    v += sB1[rm];
                sGat[Lc * 128 + g * 32 + j * 8 + b] = v;
            }
        }
        __syncthreads();

        // ---- LSTM cell update + h/out writes ----
        if (tid < 64) {
            int Lc = tid >> 5, j = (tid >> 3) & 3, b = tid & 7;
            bool actc = (Lc == 0) ? (t < S_) : (t > 0);
            if (actc) {
                int base = Lc * 128 + j * 8 + b;
                float gi = sGat[base], gf = sGat[base + 32];
                float gg = sGat[base + 64], go = sGat[base + 96];
                float c = fsig(gf) * sC[Lc * 32 + j * 8 + b] + fsig(gi) * ftanh(gg);
                float h = fsig(go) * ftanh(c);
                sC[Lc * 32 + j * 8 + b] = c;
                int u = ubase + j;
                if (Lc == 0) {
                    d_h0buf[t & 1][b][u] = h;
                    if (t == S_ - 1) out[OUT_HID + (size_t)b * H_ + u] = h;
                } else {
                    int tau = t - 1;
                    d_h1buf[tau & 1][b][u] = h;
                    out[((size_t)b * S_ + tau) * H_ + u] = h;
                    if (tau == S_ - 1) out[OUT_HID + (size_t)B_ * H_ + (size_t)b * H_ + u] = h;
                }
            }
        }
        gridbar((unsigned)(t + 1));
    }

    // ---- final cell states ----
    if (tid < 64) {
        int Lc = tid >> 5, j = (tid >> 3) & 3, b = tid & 7;
        out[OUT_CELL + (size_t)Lc * B_ * H_ + (size_t)b * H_ + ubase + j] = sC[Lc * 32 + j * 8 + b];
    }
}

// ============================================================
extern "C" void kernel_launch(void* const* d_in, const int* in_sizes, int n_in,
                              void* d_out, int out_size) {
    const float* world = (const float*)d_in[0];
    const void*  aidx  = (const void*)d_in[1];
    const float* emb   = (const float*)d_in[2];
    const float* Wp    = (const float*)d_in[3];
    const float* bp    = (const float*)d_in[4];
    const float* Wih0  = (const float*)d_in[5];
    const float* Whh0  = (const float*)d_in[6];
    const float* bih0  = (const float*)d_in[7];
    const float* bhh0  = (const float*)d_in[8];
    const float* Wih1  = (const float*)d_in[9];
    const float* Whh1  = (const float*)d_in[10];
    const float* bih1  = (const float*)d_in[11];
    const float* bhh1  = (const float*)d_in[12];
    float* out = (float*)d_out;

    float *proj_p = nullptr, *g0in_p = nullptr;
    cudaGetSymbolAddress((void**)&proj_p, d_proj);
    cudaGetSymbolAddress((void**)&g0in_p, d_g0in);

    const int smem_bytes = (16 * WS0 + 16 * WS1 + 8 * HS + 8448 + 256 + 64 + 16) * 4;
    cudaFuncSetAttribute(lstm_persistent, cudaFuncAttributeMaxDynamicSharedMemorySize, smem_bytes);

    reset_kernel<<<32, 256>>>();
    idx_kernel<<<1, 256>>>(aidx);
    embg_kernel<<<dim3(8, 32), 256>>>(emb, Wih0, bih0, bhh0);
    // proj[32768,960] = relu(world[32768,512] @ Wp[960,512]^T + bp)
    gemm_nt<<<dim3(256, 8), 256>>>(world, Wp, bp, proj_p, 960, 512, 512, 0);
    // g0in[32768,2048] = proj @ Wih0[:, :960]^T + embg[aidx]
    gemm_nt<<<dim3(256, 16), 256>>>(proj_p, Wih0, nullptr, g0in_p, 2048, 960, 1024, 1);
    lstm_persistent<<<NBLK, 256, smem_bytes>>>(Whh0, Wih1, Whh1, bih1, bhh1, out);
}

// round 16
// speedup vs baseline: 1.0029x; 1.0027x over previous
#include <cuda_runtime.h>
#include <math.h>

#define B_    8
#define S_    4096
#define H_    512
#define NBLK  128
#define NSLOT (S_ + 1)

#define OUT_HID  ((size_t)B_ * S_ * H_)        // 16,777,216
#define OUT_CELL (OUT_HID + 2 * B_ * H_)       // +8192

// ---------------- device-global scratch (allocation-free) ----------------
__device__ __align__(16) float d_proj[(size_t)32768 * 960];   // relu(world@Wp^T + bp)
__device__ __align__(16) float d_g0in[(size_t)32768 * 2048];  // input-side layer0 gates
__device__ __align__(16) float d_embg[32 * 2048];             // emb@Wih0_act^T + bih0 + bhh0
__device__ __align__(16) float d_h0buf[2][B_][H_];
__device__ __align__(16) float d_h1buf[2][B_][H_];
__device__ __align__(16) int   d_aidx32[B_ * S_];
__device__ unsigned d_barcnt;
__device__ unsigned d_bargen;

// ---------------- packed f32x2 helpers ----------------
__device__ __forceinline__ unsigned long long fma2(unsigned long long a,
                                                   unsigned long long b,
                                                   unsigned long long c) {
    unsigned long long d;
    asm("fma.rn.f32x2 %0, %1, %2, %3;" : "=l"(d) : "l"(a), "l"(b), "l"(c));
    return d;
}
__device__ __forceinline__ unsigned long long pack2(float x, float y) {
    unsigned long long d;
    asm("mov.b64 %0, {%1, %2};" : "=l"(d) : "f"(x), "f"(y));
    return d;
}
__device__ __forceinline__ float2 unpack2(unsigned long long v) {
    float2 r;
    asm("mov.b64 {%0, %1}, %2;" : "=f"(r.x), "=f"(r.y) : "l"(v));
    return r;
}
__device__ __forceinline__ float fsig(float x) { return 1.0f / (1.0f + __expf(-x)); }
__device__ __forceinline__ float ftanh(float x) { return 2.0f * fsig(2.0f * x) - 1.0f; }

// ============================================================
// reset: zero h buffers + barrier state (runs every replay)
// ============================================================
__global__ void reset_kernel() {
    int i = blockIdx.x * blockDim.x + threadIdx.x;
    if (i == 0) { d_barcnt = 0; d_bargen = 0; }
    if (i < 2 * B_ * H_) {
        ((float*)d_h0buf)[i] = 0.0f;
        ((float*)d_h1buf)[i] = 0.0f;
    }
}

// ============================================================
// idx: 4-way dtype detection (int64 / float32 / float64 / int32)
// + masked conversion to int32. For each candidate encoding we
// test "every element is integral and in [0,32)". The encodings
// are mutually exclusive on non-degenerate data:
//   - ints read as floats -> denormals (floor != value)
//   - floats read as ints -> huge magnitudes
//   - f32 pairs read as f64 (and vice versa) -> non-integral/huge
// Indices are masked &31 so gathers can never go OOB.
// ============================================================
__global__ void idx_kernel(const void* __restrict__ raw) {
    __shared__ int ok64, okf32, okf64;
    if (threadIdx.x == 0) { ok64 = 1; okf32 = 1; okf64 = 1; }
    __syncthreads();
    const long long* p64 = (const long long*)raw;
    const int*       p32 = (const int*)raw;
    // 8-byte interpretations: exactly 128 KB read (valid for int32/f32 too)
    for (int k = threadIdx.x; k < B_ * S_ / 2; k += blockDim.x) {
        long long v = p64[k];
        if (v < 0 || v >= 32) ok64 = 0;
        double d = __longlong_as_double(v);
        if (!(d >= 0.0 && d < 32.0 && d == floor(d))) okf64 = 0;
    }
    // 4-byte interpretation as float32
    for (int k = threadIdx.x; k < B_ * S_; k += blockDim.x) {
        float f = __int_as_float(p32[k]);
        if (!(f >= 0.0f && f < 32.0f && f == floorf(f))) okf32 = 0;
    }
    __syncthreads();
    if (ok64) {
        for (int k = threadIdx.x; k < B_ * S_; k += blockDim.x)
            d_aidx32[k] = ((int)p64[k]) & 31;
    } else if (okf32) {
        for (int k = threadIdx.x; k < B_ * S_; k += blockDim.x)
            d_aidx32[k] = ((int)__int_as_float(p32[k])) & 31;
    } else if (okf64) {
        for (int k = threadIdx.x; k < B_ * S_ / 2; k += blockDim.x) {
            // one f64 per logical element
        }
        for (int k = threadIdx.x; k < B_ * S_; k += blockDim.x)
            d_aidx32[k] = ((int)__longlong_as_double(p64[k])) & 31;
    } else {  // int32
        for (int k = threadIdx.x; k < B_ * S_; k += blockDim.x)
            d_aidx32[k] = p32[k] & 31;
    }
}

// ============================================================
// embg[a][n] = sum_j emb[a][j] * Wih0[n][960+j] + bih0[n] + bhh0[n]
// ============================================================
__global__ void embg_kernel(const float* __restrict__ emb, const float* __restrict__ Wih0,
                            const float* __restrict__ bih0, const float* __restrict__ bhh0) {
    int n = blockIdx.x * blockDim.x + threadIdx.x;   // 0..2047
    int a = blockIdx.y;                              // 0..31
    float s = bih0[n] + bhh0[n];
    const float* w = Wih0 + (size_t)n * 1024 + 960;
    const float* e = emb + a * 64;
#pragma unroll 16
    for (int j = 0; j < 64; j++) s += e[j] * w[j];
    d_embg[a * 2048 + n] = s;
}

// ============================================================
// NT GEMM: C[m][n] = dot(A[m, 0:K], W[n, 0:K])  (+epilogue)
// mode 0: C = relu(acc + bias[n]),          C ld = N
// mode 1: C = acc + embg[d_aidx32[m]][n],   C ld = 2048
// BM=BN=128, BK=16, 256 threads, 8x8 micro-tile, f32x2 FFMA
// ============================================================
__global__ __launch_bounds__(256, 2)
void gemm_nt(const float* __restrict__ A, const float* __restrict__ W,
             const float* __restrict__ bias,
             float* __restrict__ C, int N, int K, int ldw, int mode) {
    __shared__ __align__(16) float As[16][132];
    __shared__ __align__(16) float Ws[16][132];
    int tid = threadIdx.x;
    int m0 = blockIdx.x * 128, n0 = blockIdx.y * 128;
    int tx = tid & 15, ty = tid >> 4;

    unsigned long long acc[8][4];
#pragma unroll
    for (int i = 0; i < 8; i++)
#pragma unroll
        for (int j = 0; j < 4; j++) acc[i][j] = 0ULL;

    for (int k0 = 0; k0 < K; k0 += 16) {
#pragma unroll
        for (int j = 0; j < 2; j++) {
            int id = tid + 256 * j;               // 0..511
            int row = id >> 2, c4 = (id & 3) * 4;
            float4 v = *(const float4*)&A[(size_t)(m0 + row) * K + k0 + c4];
            As[c4 + 0][row] = v.x; As[c4 + 1][row] = v.y;
            As[c4 + 2][row] = v.z; As[c4 + 3][row] = v.w;
        }
#pragma unroll
        for (int j = 0; j < 2; j++) {
            int id = tid + 256 * j;
            int row = id >> 2, c4 = (id & 3) * 4;
            float4 v = make_float4(0.f, 0.f, 0.f, 0.f);
            if (n0 + row < N)
                v = *(const float4*)&W[(size_t)(n0 + row) * ldw + k0 + c4];
            Ws[c4 + 0][row] = v.x; Ws[c4 + 1][row] = v.y;
            Ws[c4 + 2][row] = v.z; Ws[c4 + 3][row] = v.w;
        }
        __syncthreads();
#pragma unroll
        for (int k = 0; k < 16; k++) {
            float __align__(16) a[8];
            *(float4*)&a[0] = *(const float4*)&As[k][ty * 8];
            *(float4*)&a[4] = *(const float4*)&As[k][ty * 8 + 4];
            ulonglong2 w01 = *(const ulonglong2*)&Ws[k][tx * 8];
            ulonglong2 w23 = *(const ulonglong2*)&Ws[k][tx * 8 + 4];
#pragma unroll
            for (int i = 0; i < 8; i++) {
                unsigned long long a2 = pack2(a[i], a[i]);
                acc[i][0] = fma2(a2, w01.x, acc[i][0]);
                acc[i][1] = fma2(a2, w01.y, acc[i][1]);
                acc[i][2] = fma2(a2, w23.x, acc[i][2]);
                acc[i][3] = fma2(a2, w23.y, acc[i][3]);
            }
        }
        __syncthreads();
    }

#pragma unroll
    for (int i = 0; i < 8; i++) {
        int m = m0 + ty * 8 + i;
        float __align__(16) c[8];
#pragma unroll
        for (int j = 0; j < 4; j++) {
            float2 p = unpack2(acc[i][j]);
            c[2 * j] = p.x; c[2 * j + 1] = p.y;
        }
        if (mode == 0) {
#pragma unroll
            for (int j = 0; j < 8; j++) {
                int n = n0 + tx * 8 + j;
                if (n < N) {
                    float v = c[j] + __ldg(&bias[n]);
                    C[(size_t)m * N + n] = fmaxf(v, 0.0f);
                }
            }
        } else {
            int a = d_aidx32[m];                       // pre-masked to [0,31]
            const float* eg = d_embg + (size_t)a * 2048 + n0 + tx * 8;
#pragma unroll
            for (int j = 0; j < 8; j++) c[j] += __ldg(&eg[j]);
            *(float4*)&C[(size_t)m * 2048 + n0 + tx * 8] = *(float4*)&c[0];
            *(float4*)&C[(size_t)m * 2048 + n0 + tx * 8 + 4] = *(float4*)&c[4];
        }
    }
}

// ============================================================
// Grid barrier with proper acquire/release semantics.
// __syncthreads makes all block writes visible to thread 0;
// atom.release publishes them chip-wide; pollers use ld.acquire.
// The barcnt reset is sequenced before the bargen release-store,
// so no next-generation arrival can race the reset.
// ============================================================
__device__ __forceinline__ void gridbar(unsigned gen) {
    __syncthreads();
    if (threadIdx.x == 0) {
        unsigned a;
        asm volatile("atom.release.gpu.global.add.u32 %0, [%1], %2;"
                     : "=r"(a) : "l"(&d_barcnt), "r"(1u) : "memory");
        if (a == NBLK - 1) {
            asm volatile("st.relaxed.gpu.global.u32 [%0], %1;"
                         :: "l"(&d_barcnt), "r"(0u) : "memory");
            asm volatile("st.release.gpu.global.u32 [%0], %1;"
                         :: "l"(&d_bargen), "r"(gen) : "memory");
        } else {
            unsigned g;
            do {
                asm volatile("ld.acquire.gpu.global.u32 %0, [%1];"
                             : "=r"(g) : "l"(&d_bargen) : "memory");
            } while (g < gen);
        }
    }
    __syncthreads();
}

#define WS0 516
#define WS1 1044
#define HS  1044

__global__ __launch_bounds__(256, 1)
void lstm_persistent(const float* __restrict__ Whh0, const float* __restrict__ Wih1,
                     const float* __restrict__ Whh1, const float* __restrict__ bih1,
                     const float* __restrict__ bhh1, float* __restrict__ out) {
    extern __shared__ float sm[];
    float* sW0  = sm;                   // 16 * 516  = 8256
    float* sW1  = sW0 + 16 * WS0;       // 16 * 1044 = 16704
    float* sHc  = sW1 + 16 * WS1;       // 8 * 1044  = 8352 ([0:512)=h0prev, [512:1024)=h1(t-2))
    float* sRed = sHc + 8 * HS;         // 2*16*8*33 = 8448
    float* sGat = sRed + 8448;          // 2*4*4*8   = 256
    float* sC   = sGat + 256;           // 64
    float* sB1  = sC + 64;              // 16

    const int tid = threadIdx.x, bk = blockIdx.x;
    const int ubase = bk * 4;

    // ---- load this block's recurrent weights into SMEM ----
    for (int idx = tid; idx < 2048; idx += 256) {       // Whh0: 16 rows x 512
        int rr = idx >> 7, c4 = (idx & 127) * 4;
        int grow = ((rr >> 2) << 9) + ubase + (rr & 3);
        *(float4*)&sW0[rr * WS0 + c4] = *(const float4*)&Whh0[(size_t)grow * 512 + c4];
    }
    for (int idx = tid; idx < 4096; idx += 256) {       // [Wih1|Whh1]: 16 rows x 1024
        int rr = idx >> 8, k = (idx & 255) * 4;
        int grow = ((rr >> 2) << 9) + ubase + (rr & 3);
        float4 v = (k < 512) ? *(const float4*)&Wih1[(size_t)grow * 512 + k]
                             : *(const float4*)&Whh1[(size_t)grow * 512 + k - 512];
        *(float4*)&sW1[rr * WS1 + k] = v;
    }
    if (tid < 16) {
        int grow = ((tid >> 2) << 9) + ubase + (tid & 3);
        sB1[tid] = bih1[grow] + bhh1[grow];
    }
    if (tid < 64) sC[tid] = 0.0f;
    __syncthreads();

    // dot-phase thread roles (warps 0-3: layer0, warps 4-7: layer1)
    const int L = tid >> 7;
    const int t2 = tid & 127;
    const int rg = t2 >> 5, seg = t2 & 31;
    const float* wbase = (L == 0) ? (sW0 + rg * 4 * WS0) : (sW1 + rg * 4 * WS1);
    const int wstr = (L == 0) ? WS0 : WS1;
    const int niter = (L == 0) ? 4 : 8;

    for (int t = 0; t < NSLOT; t++) {
        // ---- stage h0(t-1), h1(t-2) from L2 (bypass stale L1) ----
        const int p0 = (t + 1) & 1, p1 = t & 1;
        for (int idx = tid; idx < 2048; idx += 256) {
            int b = (idx >> 7) & 7, c4 = (idx & 127) * 4;
            if (idx < 1024)
                *(float4*)&sHc[b * HS + c4] = __ldcg((const float4*)&d_h0buf[p0][b][c4]);
            else
                *(float4*)&sHc[b * HS + 512 + c4] = __ldcg((const float4*)&d_h1buf[p1][b][c4]);
        }
        __syncthreads();

        // ---- dot products: 4 rows x 8 batches per thread ----
        bool act = (L == 0) ? (t < S_) : (t > 0);
        if (act) {
            unsigned long long acc[4][8];
#pragma unroll
            for (int r = 0; r < 4; r++)
#pragma unroll
                for (int b = 0; b < 8; b++) acc[r][b] = 0ULL;

            for (int i = 0; i < niter; i++) {
                int k = (seg << 2) + (i << 7);
                ulonglong2 w0v = *(const ulonglong2*)(wbase + k);
                ulonglong2 w1v = *(const ulonglong2*)(wbase + wstr + k);
                ulonglong2 w2v = *(const ulonglong2*)(wbase + 2 * wstr + k);
                ulonglong2 w3v = *(const ulonglong2*)(wbase + 3 * wstr + k);
#pragma unroll
                for (int b = 0; b < 8; b++) {
                    ulonglong2 h = *(const ulonglong2*)(sHc + b * HS + k);
                    acc[0][b] = fma2(w0v.x, h.x, acc[0][b]);
                    acc[0][b] = fma2(w0v.y, h.y, acc[0][b]);
                    acc[1][b] = fma2(w1v.x, h.x, acc[1][b]);
                    acc[1][b] = fma2(w1v.y, h.y, acc[1][b]);
                    acc[2][b] = fma2(w2v.x, h.x, acc[2][b]);
                    acc[2][b] = fma2(w2v.y, h.y, acc[2][b]);
                    acc[3][b] = fma2(w3v.x, h.x, acc[3][b]);
                    acc[3][b] = fma2(w3v.y, h.y, acc[3][b]);
                }
            }
#pragma unroll
            for (int r = 0; r < 4; r++)
#pragma unroll
                for (int b = 0; b < 8; b++) {
                    float2 p = unpack2(acc[r][b]);
                    sRed[((L * 16 + rg * 4 + r) * 8 + b) * 33 + seg] = p.x + p.y;
                }
        }
        __syncthreads();

        // ---- combine partials -> gate values ----
        {
            int Lc = tid >> 7, rm = (tid >> 3) & 15, b = tid & 7;
            bool actc = (Lc == 0) ? (t < S_) : (t > 0);
            if (actc) {
                const float* rp = sRed + ((Lc * 16 + rm) * 8 + b) * 33;
                float v = 0.0f;
#pragma unroll
                for (int s3 = 0; s3 < 32; s3++) v += rp[s3];
                int g = rm >> 2, j = rm & 3;
                if (Lc == 0)
                    v += __ldg(&d_g0in[((size_t)b * S_ + t) * 2048 + (g << 9) + ubase + j]);
                else
                    v += sB1[rm];
                sGat[Lc * 128 + g * 32 + j * 8 + b] = v;
            }
        }
        __syncthreads();

        // ---- LSTM cell update + h/out writes ----
        if (tid < 64) {
            int Lc = tid >> 5, j = (tid >> 3) & 3, b = tid & 7;
            bool actc = (Lc == 0) ? (t < S_) : (t > 0);
            if (actc) {
                int base = Lc * 128 + j * 8 + b;
                float gi = sGat[base], gf = sGat[base + 32];
                float gg = sGat[base + 64], go = sGat[base + 96];
                float c = fsig(gf) * sC[Lc * 32 + j * 8 + b] + fsig(gi) * ftanh(gg);
                float h = fsig(go) * ftanh(c);
                sC[Lc * 32 + j * 8 + b] = c;
                int u = ubase + j;
                if (Lc == 0) {
                    d_h0buf[t & 1][b][u] = h;
                    if (t == S_ - 1) out[OUT_HID + (size_t)b * H_ + u] = h;
                } else {
                    int tau = t - 1;
                    d_h1buf[tau & 1][b][u] = h;
                    out[((size_t)b * S_ + tau) * H_ + u] = h;
                    if (tau == S_ - 1) out[OUT_HID + (size_t)B_ * H_ + (size_t)b * H_ + u] = h;
                }
            }
        }
        gridbar((unsigned)(t + 1));
    }

    // ---- final cell states ----
    if (tid < 64) {
        int Lc = tid >> 5, j = (tid >> 3) & 3, b = tid & 7;
        out[OUT_CELL + (size_t)Lc * B_ * H_ + (size_t)b * H_ + ubase + j] = sC[Lc * 32 + j * 8 + b];
    }
}

// ============================================================
extern "C" void kernel_launch(void* const* d_in, const int* in_sizes, int n_in,
                              void* d_out, int out_size) {
    const float* world = (const float*)d_in[0];
    const void*  aidx  = (const void*)d_in[1];
    const float* emb   = (const float*)d_in[2];
    const float* Wp    = (const float*)d_in[3];
    const float* bp    = (const float*)d_in[4];
    const float* Wih0  = (const float*)d_in[5];
    const float* Whh0  = (const float*)d_in[6];
    const float* bih0  = (const float*)d_in[7];
    const float* bhh0  = (const float*)d_in[8];
    const float* Wih1  = (const float*)d_in[9];
    const float* Whh1  = (const float*)d_in[10];
    const float* bih1  = (const float*)d_in[11];
    const float* bhh1  = (const float*)d_in[12];
    float* out = (float*)d_out;

    float *proj_p = nullptr, *g0in_p = nullptr;
    cudaGetSymbolAddress((void**)&proj_p, d_proj);
    cudaGetSymbolAddress((void**)&g0in_p, d_g0in);

    const int smem_bytes = (16 * WS0 + 16 * WS1 + 8 * HS + 8448 + 256 + 64 + 16) * 4;
    cudaFuncSetAttribute(lstm_persistent, cudaFuncAttributeMaxDynamicSharedMemorySize, smem_bytes);

    reset_kernel<<<32, 256>>>();
    idx_kernel<<<1, 256>>>(aidx);
    embg_kernel<<<dim3(8, 32), 256>>>(emb, Wih0, bih0, bhh0);
    // proj[32768,960] = relu(world[32768,512] @ Wp[960,512]^T + bp)
    gemm_nt<<<dim3(256, 8), 256>>>(world, Wp, bp, proj_p, 960, 512, 512, 0);
    // g0in[32768,2048] = proj @ Wih0[:, :960]^T + embg[aidx]
    gemm_nt<<<dim3(256, 16), 256>>>(proj_p, Wih0, nullptr, g0in_p, 2048, 960, 1024, 1);
    lstm_persistent<<<NBLK, 256, smem_bytes>>>(Whh0, Wih1, Whh1, bih1, bhh1, out);
}